// round 7
// baseline (speedup 1.0000x reference)
#include <cuda_runtime.h>
#include <math_constants.h>

// ---------------------------------------------------------------------------
// APPM: 13-ratio sliding-window avg pooling (smem SAT) + 3-group greedy NMS
// (picks 2/3/2, IoU 0.25), batch 256.
//
// Round-7: (a) NMS scans read scores from gmem ws (1 LDG/window) instead of
// 4-float SAT recompute -> L1 traffic cut ~4x in NMS; (b) argmax via per-tile
// FMNMX tree + lazy index (candidate tile off saved on improvement, single
// endgame rescan resolves the exact index) -> removes the FSETP->SEL serial
// chain from all hot loops.
//
// Output layout (float32):
//   [0,1792)               proposalN_indices  (256 x 7) as float
//   [1792,3584)            proposalN_windows_scores (256 x 7)
//   [3584, 3584+256*96981) window_scores (256 x 96981)
// ---------------------------------------------------------------------------

#define FEAT   112
#define SATN   113
#define SATP   116            // padded SAT row stride (multiple of 4)
#define NRAT   13
#define NBATCH 256
#define NTOTAL 96981
#define PROPN  7
#define NTH    1024
#define NYS    1160           // per-slot hy-table floats (padded nc summed)
#define NEGINF (-CUDART_INF_F)

__host__ __device__ constexpr int cRH(int r) {
    constexpr int a[NRAT] = {16,12,20,24,20,28,32,24,40,28,40,28,36};
    return a[r];
}
__host__ __device__ constexpr int cRW(int r) {
    constexpr int a[NRAT] = {16,20,12,24,28,20,32,40,24,40,28,36,28};
    return a[r];
}
__host__ __device__ constexpr int cBASE(int r) {
    constexpr int a[NRAT+1] = {0,9409,18802,28195,36116,44021,51926,58487,
                               64984,71481,77686,83891,90436,96981};
    return a[r];
}
// prefix sums of padded-to-4 nc (nc = 113-RW)
__host__ __device__ constexpr int cYQ(int r) {
    constexpr int a[NRAT] = {0,100,196,300,392,480,576,660,736,828,904,992,1072};
    return a[r];
}

// dynamic smem (floats): SAT[113*116] | HYS[2*NYS]
#define SMEM_FLOATS (SATN*SATP + 2*NYS)

// warp-level pairwise merge (max score, min idx on tie)
__device__ __forceinline__ void wmerge(float& b, int& bi) {
    #pragma unroll
    for (int o = 16; o > 0; o >>= 1) {
        float os = __shfl_down_sync(0xffffffffu, b, o);
        int   oi = __shfl_down_sync(0xffffffffu, bi, o);
        if (os > b || (os == b && oi < bi)) { b = os; bi = oi; }
    }
}

// decode a winning window index into its box + area (lane0 only)
__device__ __forceinline__ void decode_box(int bidx, float* box, float* sa) {
    int rh = cRH(0), rw = cRW(0), bb = 0;
    #pragma unroll
    for (int r = 1; r < NRAT; r++)
        if (bidx >= cBASE(r)) { rh = cRH(r); rw = cRW(r); bb = cBASE(r); }
    int off = bidx - bb;
    int nc = SATN - rw;
    int xi = off / nc, yi = off - xi * nc;
    float x0u = (float)(4 * xi - 1), y0u = (float)(4 * yi - 1);
    float cx0 = fmaxf(x0u, 0.0f), cy0 = fmaxf(y0u, 0.0f);
    float cx1 = x0u + (float)(4 * rh);
    float cy1 = y0u + (float)(4 * rw);
    box[0] = cx0; box[1] = cy0; box[2] = cx1; box[3] = cy1;
    *sa = (cx1 - cx0 + 1.0f) * (cy1 - cy0 + 1.0f);
}

// fill hy table (full yi range incl. border yi=0; zero pad) for [R0,R1)
template<int R0, int R1>
__device__ __forceinline__ void fill_hys(
    int slot, int tid, float* HYS, const float* box)
{
    float by0 = box[1], by1 = box[3];
    #pragma unroll
    for (int r = R0; r < R1; r++) {
        const int rw = cRW(r);
        const int nc = SATN - rw;
        const int ncp = (nc + 3) & ~3;
        if (tid < ncp) {
            float h = 0.0f;
            if (tid < nc) {
                float y0u = (float)(4 * tid - 1);
                float y0 = fmaxf(y0u, 0.0f);
                float y1 = y0u + (float)(4 * rw);
                h = fmaxf(fminf(y1, by1) - fmaxf(y0, by0) + 1.0f, 0.0f);
            }
            HYS[slot * NYS + cYQ(r) + tid] = h;
        }
    }
}

// ---------------------------------------------------------------------------
// NMS main scan, ratios [R0,R1), P priors (1 or 2). Scores read from ws
// (LDG). Suppress iff 5*inter > areaW + selarea (exact ints in fp32 ==
// reference IoU>0.25). Tracks (best score, candidate tile start idx) only.
// ---------------------------------------------------------------------------
template<int R0, int R1, int P>
__device__ __forceinline__ void nms_scan(
    const float* __restrict__ ws, const float* __restrict__ HYS,
    float bx0a, float bx1a, float saA,
    float bx0b, float bx1b, float saB,
    int tid, float& best, int& cand)
{
    #pragma unroll
    for (int r = R0; r < R1; r++) {
        const int rh = cRH(r), rw = cRW(r);
        const int nr = SATN - rh, nc = SATN - rw;
        const int nq = (nc + 3) >> 2;          // nc % 4 == 1: last tile = 1 win
        const int ntile = nr * nq;
        const int base = cBASE(r);
        const float frh  = (float)(4 * rh),     frw  = (float)(4 * rw);
        const float frh1 = frh + 1.0f,          frw1 = frw + 1.0f;
        const float* hys0 = HYS + cYQ(r);
        const float* hys1 = HYS + NYS + cYQ(r);
        const float* wsr = ws + base;

        #pragma unroll 1
        for (int t = tid; t < ntile; t += NTH) {
            int xi = t / nq;                   // nq const -> mul/shift
            int q  = t - xi * nq;
            int yq = q << 2;
            int o  = xi * nc + yq;
            bool full = (q != nq - 1);
            // guarded loads (partial tile would run past this ratio/image)
            float s0 = wsr[o];
            float s1 = full ? wsr[o + 1] : NEGINF;
            float s2 = full ? wsr[o + 2] : NEGINF;
            float s3 = full ? wsr[o + 3] : NEGINF;
            float x0u = (float)(4 * xi - 1);
            float x0 = fmaxf(x0u, 0.0f), x1 = x0u + frh;
            float ax = (xi == 0) ? frh : frh1;
            float w5a = 5.0f * fmaxf(fminf(x1, bx1a) - fmaxf(x0, bx0a) + 1.0f, 0.0f);
            float rhsa  = fmaf(ax, frw1, saA);
            float rhsa0 = fmaf(ax, frw,  saA);     // yi == 0 (ay = frw)
            float4 h4 = *(const float4*)(hys0 + yq);
            bool k0 = (w5a * h4.x <= ((yq == 0) ? rhsa0 : rhsa));
            bool k1 = (w5a * h4.y <= rhsa);
            bool k2 = (w5a * h4.z <= rhsa);
            bool k3 = (w5a * h4.w <= rhsa);
            if constexpr (P >= 2) {
                float w5b = 5.0f * fmaxf(fminf(x1, bx1b) - fmaxf(x0, bx0b) + 1.0f, 0.0f);
                float rhsb  = fmaf(ax, frw1, saB);
                float rhsb0 = fmaf(ax, frw,  saB);
                float4 g4 = *(const float4*)(hys1 + yq);
                k0 &= (w5b * g4.x <= ((yq == 0) ? rhsb0 : rhsb));
                k1 &= (w5b * g4.y <= rhsb);
                k2 &= (w5b * g4.z <= rhsb);
                k3 &= (w5b * g4.w <= rhsb);
            }
            float q0 = k0 ? s0 : NEGINF;
            float q1 = k1 ? s1 : NEGINF;
            float q2 = k2 ? s2 : NEGINF;
            float q3 = k3 ? s3 : NEGINF;
            float m = fmaxf(fmaxf(q0, q1), fmaxf(q2, q3));
            bool imp = (m > best);             // strict: keeps earliest tile
            best = fmaxf(best, m);
            if (imp) cand = base + o;
        }
    }
}

// endgame: resolve exact window index from the candidate tile (rare path)
template<int R0, int R1, int P>
__device__ __forceinline__ void nms_endgame(
    const float* __restrict__ ws, const float* __restrict__ HYS,
    float bx0a, float bx1a, float saA,
    float bx0b, float bx1b, float saB,
    float best, int cand, int& bidx)
{
    bidx = 0x7fffffff;
    if (cand < 0) return;
    #pragma unroll
    for (int r = R0; r < R1; r++) {
        if (cand >= cBASE(r) && cand < cBASE(r + 1)) {
            const int rh = cRH(r), rw = cRW(r);
            const int nc = SATN - rw;
            const int base = cBASE(r);
            const float frh  = (float)(4 * rh),     frw  = (float)(4 * rw);
            const float frh1 = frh + 1.0f,          frw1 = frw + 1.0f;
            int o  = cand - base;
            int xi = o / nc;
            int yq = o - xi * nc;
            bool full = (yq + 1 < nc);
            float s0 = ws[cand];
            float s1 = full ? ws[cand + 1] : NEGINF;
            float s2 = full ? ws[cand + 2] : NEGINF;
            float s3 = full ? ws[cand + 3] : NEGINF;
            float x0u = (float)(4 * xi - 1);
            float x0 = fmaxf(x0u, 0.0f), x1 = x0u + frh;
            float ax = (xi == 0) ? frh : frh1;
            float w5a = 5.0f * fmaxf(fminf(x1, bx1a) - fmaxf(x0, bx0a) + 1.0f, 0.0f);
            float rhsa  = fmaf(ax, frw1, saA);
            float rhsa0 = fmaf(ax, frw,  saA);
            const float* hys0 = HYS + cYQ(r);
            float4 h4 = *(const float4*)(hys0 + yq);
            bool k0 = (w5a * h4.x <= ((yq == 0) ? rhsa0 : rhsa));
            bool k1 = (w5a * h4.y <= rhsa);
            bool k2 = (w5a * h4.z <= rhsa);
            bool k3 = (w5a * h4.w <= rhsa);
            if constexpr (P >= 2) {
                const float* hys1 = HYS + NYS + cYQ(r);
                float w5b = 5.0f * fmaxf(fminf(x1, bx1b) - fmaxf(x0, bx0b) + 1.0f, 0.0f);
                float rhsb  = fmaf(ax, frw1, saB);
                float rhsb0 = fmaf(ax, frw,  saB);
                float4 g4 = *(const float4*)(hys1 + yq);
                k0 &= (w5b * g4.x <= ((yq == 0) ? rhsb0 : rhsb));
                k1 &= (w5b * g4.y <= rhsb);
                k2 &= (w5b * g4.z <= rhsb);
                k3 &= (w5b * g4.w <= rhsb);
            }
            float q0 = k0 ? s0 : NEGINF;
            float q1 = k1 ? s1 : NEGINF;
            float q2 = k2 ? s2 : NEGINF;
            float q3 = k3 ? s3 : NEGINF;
            if      (q0 == best) bidx = cand;
            else if (q1 == best) bidx = cand + 1;
            else if (q2 == best) bidx = cand + 2;
            else                 bidx = cand + 3;
        }
    }
}

// endgame for the scoring pass (no suppression)
__device__ __forceinline__ void score_endgame(
    const float* __restrict__ ws, float best, int cand, int& bidx)
{
    bidx = 0x7fffffff;
    if (cand < 0) return;
    #pragma unroll
    for (int r = 0; r < NRAT; r++) {
        if (cand >= cBASE(r) && cand < cBASE(r + 1)) {
            const int nc = SATN - cRW(r);
            int o  = cand - cBASE(r);
            int xi = o / nc;
            int yq = o - xi * nc;
            bool full = (yq + 1 < nc);
            float s0 = ws[cand];
            float s1 = full ? ws[cand + 1] : NEGINF;
            float s2 = full ? ws[cand + 2] : NEGINF;
            if      (s0 == best) bidx = cand;
            else if (s1 == best) bidx = cand + 1;
            else if (s2 == best) bidx = cand + 2;
            else                 bidx = cand + 3;
        }
    }
}

__global__ void __launch_bounds__(NTH, 2)
appm_kernel(const float* __restrict__ x, float* __restrict__ out)
{
    extern __shared__ float SH[];
    float* S   = SH;                    // SATN * SATP padded SAT
    float* HYS = SH + SATN * SATP;      // 2 slots * NYS

    __shared__ float red_s[3][32];
    __shared__ int   red_i[3][32];
    __shared__ float boxsm[4][4];       // pick0 g0/g1/g2, g1-pick1
    __shared__ float sarea[4];

    const int tid  = threadIdx.x;
    const int b    = blockIdx.x;
    const int lane = tid & 31;
    const int warp = tid >> 5;

    const float* __restrict__ xb = x + (size_t)b * (FEAT * FEAT);

    // ---- (1) SAT build (padded stride 116; cols 113-115 stay zero) --------
    for (int k = tid; k < SATN * SATP; k += NTH) {
        int i = k / SATP;
        int j = k - i * SATP;
        float v = 0.0f;
        if (i > 0 && j > 0 && j < SATN) v = xb[(i - 1) * FEAT + (j - 1)];
        S[k] = v;
    }
    __syncthreads();
    if (tid < SATN) {                   // row prefix
        float acc = 0.0f;
        float* row = S + tid * SATP;
        #pragma unroll 4
        for (int j = 1; j < SATN; j++) { acc += row[j]; row[j] = acc; }
    }
    __syncthreads();
    if (tid < SATN) {                   // column prefix (coalesced)
        float acc = 0.0f;
        #pragma unroll 4
        for (int i = 1; i < SATN; i++) {
            acc += S[i * SATP + tid];
            S[i * SATP + tid] = acc;
        }
    }
    __syncthreads();

    // ---- (2) window scores -> gmem via float4 SAT tiles, fused pick0 ------
    float* ws = out + 2 * (NBATCH * PROPN) + (size_t)b * NTOTAL;

    float bst[3] = {NEGINF, NEGINF, NEGINF};
    int   cnd[3] = {-1, -1, -1};
    int   bix[3];

    #pragma unroll
    for (int r = 0; r < NRAT; r++) {
        const int rh = cRH(r), rw = cRW(r);
        const int nr = SATN - rh, nc = SATN - rw;
        const int nq = (nc + 3) >> 2;
        const int ntile = nr * nq;
        const float inv = 1.0f / (float)(rh * rw);
        const int base = cBASE(r);
        const int g = (r < 3) ? 0 : (r < 6) ? 1 : 2;
        const int R = rh * SATP;
        float* wsr = ws + base;
        #pragma unroll 1
        for (int t = tid; t < ntile; t += NTH) {
            int xi = t / nq;
            int q  = t - xi * nq;
            int yi = q << 2;
            int a  = xi * SATP + yi;    // 16B-aligned
            float4 v0 = *(const float4*)(S + a);
            float4 v1 = *(const float4*)(S + a + rw);
            float4 v2 = *(const float4*)(S + a + R);
            float4 v3 = *(const float4*)(S + a + R + rw);
            float s0 = (v3.x - v1.x - v2.x + v0.x) * inv;
            float s1 = (v3.y - v1.y - v2.y + v0.y) * inv;
            float s2 = (v3.z - v1.z - v2.z + v0.z) * inv;
            float s3 = (v3.w - v1.w - v2.w + v0.w) * inv;
            int off = xi * nc + yi;
            bool full = (q != nq - 1);
            wsr[off] = s0;
            if (full) {
                wsr[off + 1] = s1;
                wsr[off + 2] = s2;
                wsr[off + 3] = s3;
            }
            float m1 = full ? s1 : NEGINF;
            float m2 = full ? s2 : NEGINF;
            float m3 = full ? s3 : NEGINF;
            float m = fmaxf(fmaxf(s0, m1), fmaxf(m2, m3));
            bool imp = (m > bst[g]);
            bst[g] = fmaxf(bst[g], m);
            if (imp) cnd[g] = base + off;
        }
    }
    // resolve pick0 indices (rare-path, once per group)
    score_endgame(ws, bst[0], cnd[0], bix[0]);
    score_endgame(ws, bst[1], cnd[1], bix[1]);
    score_endgame(ws, bst[2], cnd[2], bix[2]);

    // ---- (3a) batched 3-way reduction: pick0 of each group ----------------
    {
        #pragma unroll
        for (int g = 0; g < 3; g++) wmerge(bst[g], bix[g]);
        if (lane == 0)
            #pragma unroll
            for (int g = 0; g < 3; g++) { red_s[g][warp] = bst[g]; red_i[g][warp] = bix[g]; }
        __syncthreads();   // also orders ws stores before NMS reads
        if (warp == 0) {
            float bb[3]; int ii[3];
            #pragma unroll
            for (int g = 0; g < 3; g++) { bb[g] = red_s[g][lane]; ii[g] = red_i[g][lane]; wmerge(bb[g], ii[g]); }
            if (lane == 0) {
                const int slot[3] = {0, 2, 5};
                #pragma unroll
                for (int g = 0; g < 3; g++) {
                    out[b * PROPN + slot[g]] = (float)ii[g];
                    out[NBATCH * PROPN + b * PROPN + slot[g]] = bb[g];
                    decode_box(ii[g], boxsm[g], &sarea[g]);
                }
            }
        }
        __syncthreads();
    }

    // ---- (3b) hy tables (slot 0) for all 3 groups' pick0 priors ------------
    fill_hys<0, 3>(0, tid, HYS, boxsm[0]);
    fill_hys<3, 6>(0, tid, HYS, boxsm[1]);
    fill_hys<6, 13>(0, tid, HYS, boxsm[2]);
    __syncthreads();

    // ---- (3c) pick1 scans (LDG from ws; tree-max + lazy index) -------------
    float b0x0 = boxsm[0][0], b0x1 = boxsm[0][2];
    float b1x0 = boxsm[1][0], b1x1 = boxsm[1][2];
    float b2x0 = boxsm[2][0], b2x1 = boxsm[2][2];
    float sa0 = sarea[0], sa1g = sarea[1], sa2 = sarea[2];

    bst[0] = bst[1] = bst[2] = NEGINF;
    cnd[0] = cnd[1] = cnd[2] = -1;
    nms_scan<0, 3, 1>(ws, HYS, b0x0, b0x1, sa0,  0, 0, 0, tid, bst[0], cnd[0]);
    nms_scan<3, 6, 1>(ws, HYS, b1x0, b1x1, sa1g, 0, 0, 0, tid, bst[1], cnd[1]);
    nms_scan<6, 13, 1>(ws, HYS, b2x0, b2x1, sa2, 0, 0, 0, tid, bst[2], cnd[2]);
    nms_endgame<0, 3, 1>(ws, HYS, b0x0, b0x1, sa0,  0, 0, 0, bst[0], cnd[0], bix[0]);
    nms_endgame<3, 6, 1>(ws, HYS, b1x0, b1x1, sa1g, 0, 0, 0, bst[1], cnd[1], bix[1]);
    nms_endgame<6, 13, 1>(ws, HYS, b2x0, b2x1, sa2, 0, 0, 0, bst[2], cnd[2], bix[2]);

    // ---- (3d) batched reduction: pick1s; decode only g1's winner -----------
    {
        #pragma unroll
        for (int g = 0; g < 3; g++) wmerge(bst[g], bix[g]);
        if (lane == 0)
            #pragma unroll
            for (int g = 0; g < 3; g++) { red_s[g][warp] = bst[g]; red_i[g][warp] = bix[g]; }
        __syncthreads();
        if (warp == 0) {
            float bb[3]; int ii[3];
            #pragma unroll
            for (int g = 0; g < 3; g++) { bb[g] = red_s[g][lane]; ii[g] = red_i[g][lane]; wmerge(bb[g], ii[g]); }
            if (lane == 0) {
                const int slot[3] = {1, 3, 6};
                #pragma unroll
                for (int g = 0; g < 3; g++) {
                    out[b * PROPN + slot[g]] = (float)ii[g];
                    out[NBATCH * PROPN + b * PROPN + slot[g]] = bb[g];
                }
                decode_box(ii[1], boxsm[3], &sarea[3]);
            }
        }
        __syncthreads();
    }

    // ---- (3e) g1 pick2: slot-1 tables, 2-prior scan -------------------------
    fill_hys<3, 6>(1, tid, HYS, boxsm[3]);
    __syncthreads();
    float b3x0 = boxsm[3][0], b3x1 = boxsm[3][2];
    float nb = NEGINF; int ncand = -1; int ni;
    nms_scan<3, 6, 2>(ws, HYS, b1x0, b1x1, sa1g,
                      b3x0, b3x1, sarea[3], tid, nb, ncand);
    nms_endgame<3, 6, 2>(ws, HYS, b1x0, b1x1, sa1g,
                         b3x0, b3x1, sarea[3], nb, ncand, ni);
    {
        wmerge(nb, ni);
        if (lane == 0) { red_s[0][warp] = nb; red_i[0][warp] = ni; }
        __syncthreads();
        if (warp == 0) {
            nb = red_s[0][lane]; ni = red_i[0][lane];
            wmerge(nb, ni);
            if (lane == 0) {
                out[b * PROPN + 4] = (float)ni;
                out[NBATCH * PROPN + b * PROPN + 4] = nb;
            }
        }
    }
}

extern "C" void kernel_launch(void* const* d_in, const int* in_sizes, int n_in,
                              void* d_out, int out_size) {
    const float* x = (const float*)d_in[0];
    float* out = (float*)d_out;
    (void)in_sizes; (void)n_in; (void)out_size;

    const int smem = SMEM_FLOATS * (int)sizeof(float);  // 61712 B
    cudaFuncSetAttribute(appm_kernel, cudaFuncAttributeMaxDynamicSharedMemorySize, smem);
    appm_kernel<<<NBATCH, NTH, smem>>>(x, out);
}

// round 8
// speedup vs baseline: 1.0364x; 1.0364x over previous
#include <cuda_runtime.h>
#include <math_constants.h>

// ---------------------------------------------------------------------------
// APPM: 13-ratio sliding-window avg pooling (smem SAT) + 3-group greedy NMS
// (picks 2/3/2, IoU 0.25), batch 256.
//
// Round-8: single full pass. Scoring is warp-per-row; each row's (max, argmax)
// is cached in smem (1121 rows). NMS picks use row-level pruning:
//   phase 1: rows with zero x-overlap vs all priors are unsuppressed -> their
//            cached (rowmax, rowarg) is the candidate; CTA-reduce -> LB.
//   phase 2: deferred rows with rowmax >= LB (rare) get exact re-evaluation
//            from the SAT (bit-identical expression -> sound pruning).
// Suppression test is division-free: 5*inter > areaW + selarea (exact small
// ints in fp32 == reference IoU > 0.25).
//
// Output layout (float32):
//   [0,1792)               proposalN_indices  (256 x 7) as float
//   [1792,3584)            proposalN_windows_scores (256 x 7)
//   [3584, 3584+256*96981) window_scores (256 x 96981)
// ---------------------------------------------------------------------------

#define FEAT   112
#define SATN   113
#define SATP   116            // padded SAT row stride (multiple of 4)
#define NRAT   13
#define NBATCH 256
#define NTOTAL 96981
#define PROPN  7
#define NTH    1024
#define NROWS  1121           // total rows over all 13 ratios
#define NEGINF (-CUDART_INF_F)

__host__ __device__ constexpr int cRH(int r) {
    constexpr int a[NRAT] = {16,12,20,24,20,28,32,24,40,28,40,28,36};
    return a[r];
}
__host__ __device__ constexpr int cRW(int r) {
    constexpr int a[NRAT] = {16,20,12,24,28,20,32,40,24,40,28,36,28};
    return a[r];
}
__host__ __device__ constexpr int cBASE(int r) {
    constexpr int a[NRAT+1] = {0,9409,18802,28195,36116,44021,51926,58487,
                               64984,71481,77686,83891,90436,96981};
    return a[r];
}
// prefix sums of nr = 113-RH  (global row id base per ratio)
__host__ __device__ constexpr int cXO(int r) {
    constexpr int a[NRAT+1] = {0,97,198,291,380,473,558,639,728,801,886,959,1044,1121};
    return a[r];
}

// dynamic smem (floats): SAT[113*116] | RMAX[1121] | RARG[1121]
#define SMEM_FLOATS (SATN*SATP + 2*NROWS)

// warp-level pairwise merge (max score, min idx on tie); result in lane 0
__device__ __forceinline__ void wmerge(float& b, int& bi) {
    #pragma unroll
    for (int o = 16; o > 0; o >>= 1) {
        float os = __shfl_down_sync(0xffffffffu, b, o);
        int   oi = __shfl_down_sync(0xffffffffu, bi, o);
        if (os > b || (os == b && oi < bi)) { b = os; bi = oi; }
    }
}

// decode a winning window index into its box + area (lane0 only)
__device__ __forceinline__ void decode_box(int bidx, float* box, float* sa) {
    int rh = cRH(0), rw = cRW(0), bb = 0;
    #pragma unroll
    for (int r = 1; r < NRAT; r++)
        if (bidx >= cBASE(r)) { rh = cRH(r); rw = cRW(r); bb = cBASE(r); }
    int off = bidx - bb;
    int nc = SATN - rw;
    int xi = off / nc, yi = off - xi * nc;
    float x0u = (float)(4 * xi - 1), y0u = (float)(4 * yi - 1);
    float cx0 = fmaxf(x0u, 0.0f), cy0 = fmaxf(y0u, 0.0f);
    float cx1 = x0u + (float)(4 * rh);
    float cy1 = y0u + (float)(4 * rw);
    box[0] = cx0; box[1] = cy0; box[2] = cx1; box[3] = cy1;
    *sa = (cx1 - cx0 + 1.0f) * (cy1 - cy0 + 1.0f);
}

// ---------------------------------------------------------------------------
// phase 1: thread tid <-> group-local row. If x-overlap with every prior is
// zero, candidate = cached (rowmax, rowarg); else defer for phase 2.
// ---------------------------------------------------------------------------
template<int R0, int R1, int P>
__device__ __forceinline__ void pick_phase1(
    const float* __restrict__ RMAX, const int* __restrict__ RARG,
    float ax0a, float ax1a, float ax0b, float ax1b,
    int tid, float& cs, int& ci, bool& defer, float& rmax)
{
    cs = NEGINF; ci = 0x7fffffff; defer = false; rmax = NEGINF;
    const int gb = cXO(R0);
    const int NRg = cXO(R1) - gb;
    if (tid >= NRg) return;
    rmax = RMAX[gb + tid];
    int rarg = RARG[gb + tid];
    float ov = 0.0f;
    #pragma unroll
    for (int r = R0; r < R1; r++) {
        int xi = tid - (cXO(r) - gb);
        if (xi >= 0 && xi < SATN - cRH(r)) {
            float frh = (float)(4 * cRH(r));
            float x0u = (float)(4 * xi - 1);
            float x0 = fmaxf(x0u, 0.0f), x1 = x0u + frh;
            ov += fmaxf(fminf(x1, ax1a) - fmaxf(x0, ax0a) + 1.0f, 0.0f);
            if constexpr (P >= 2)
                ov += fmaxf(fminf(x1, ax1b) - fmaxf(x0, ax0b) + 1.0f, 0.0f);
        }
    }
    if (ov == 0.0f) { cs = rmax; ci = rarg; }
    else defer = true;
}

// ---------------------------------------------------------------------------
// phase 2: exact evaluation of a deferred row (only if rowmax >= LB).
// Scores recomputed from SAT with the EXACT scoring expression.
// ---------------------------------------------------------------------------
template<int R0, int R1, int P>
__device__ __forceinline__ void pick_phase2(
    const float* __restrict__ S,
    float ax0a, float ax1a, float ay0a, float ay1a, float saa,
    float ax0b, float ax1b, float ay0b, float ay1b, float sab,
    int tid, bool defer, float rmax, float LBs, int LBi,
    float& cs, int& ci)
{
    cs = LBs; ci = LBi;
    if (!defer || rmax < LBs) return;
    const int gb = cXO(R0);
    #pragma unroll
    for (int r = R0; r < R1; r++) {
        int xi = tid - (cXO(r) - gb);
        if (xi >= 0 && xi < SATN - cRH(r)) {
            const int rh = cRH(r), rw = cRW(r), nc = SATN - rw;
            const int nq = (nc + 3) >> 2;
            const float inv = 1.0f / (float)(rh * rw);
            const int R_ = rh * SATP, base = cBASE(r);
            const float frh = (float)(4 * rh), frw = (float)(4 * rw);
            const float ax = (xi == 0) ? frh : frh + 1.0f;
            float x0u = (float)(4 * xi - 1);
            float x0 = fmaxf(x0u, 0.0f), x1 = x0u + frh;
            float w5a = 5.0f * fmaxf(fminf(x1, ax1a) - fmaxf(x0, ax0a) + 1.0f, 0.0f);
            float w5b = 0.0f;
            if constexpr (P >= 2)
                w5b = 5.0f * fmaxf(fminf(x1, ax1b) - fmaxf(x0, ax0b) + 1.0f, 0.0f);
            const int rowoff = base + xi * nc;
            #pragma unroll 1
            for (int q = 0; q < nq; q++) {
                int a = xi * SATP + (q << 2);
                float4 v0 = *(const float4*)(S + a);
                float4 v1 = *(const float4*)(S + a + rw);
                float4 v2 = *(const float4*)(S + a + R_);
                float4 v3 = *(const float4*)(S + a + R_ + rw);
                float sv[4];
                sv[0] = (v3.x - v1.x - v2.x + v0.x) * inv;
                sv[1] = (v3.y - v1.y - v2.y + v0.y) * inv;
                sv[2] = (v3.z - v1.z - v2.z + v0.z) * inv;
                sv[3] = (v3.w - v1.w - v2.w + v0.w) * inv;
                #pragma unroll
                for (int e = 0; e < 4; e++) {
                    int yi = (q << 2) + e;
                    if (yi < nc) {
                        float ay = (yi == 0) ? frw : frw + 1.0f;
                        float y0u = (float)(4 * yi - 1);
                        float y0 = fmaxf(y0u, 0.0f), y1 = y0u + frw;
                        float hya = fmaxf(fminf(y1, ay1a) - fmaxf(y0, ay0a) + 1.0f, 0.0f);
                        bool sup = (w5a * hya > fmaf(ax, ay, saa));
                        if constexpr (P >= 2) {
                            float hyb = fmaxf(fminf(y1, ay1b) - fmaxf(y0, ay0b) + 1.0f, 0.0f);
                            sup |= (w5b * hyb > fmaf(ax, ay, sab));
                        }
                        int idx = rowoff + yi;
                        if (!sup && (sv[e] > cs || (sv[e] == cs && idx < ci))) {
                            cs = sv[e]; ci = idx;
                        }
                    }
                }
            }
        }
    }
}

__global__ void __launch_bounds__(NTH, 2)
appm_kernel(const float* __restrict__ x, float* __restrict__ out)
{
    extern __shared__ float SH[];
    float* S    = SH;                     // SATN * SATP padded SAT
    float* RMAX = SH + SATN * SATP;       // per-row max
    int*   RARG = (int*)(RMAX + NROWS);   // per-row argmax (global window idx)

    __shared__ float red_s[3][32];
    __shared__ int   red_i[3][32];
    __shared__ float boxsm[4][4];         // pick0 g0/g1/g2, g1-pick1
    __shared__ float sarea[4];
    __shared__ float LBs[3];
    __shared__ int   LBi[3];

    const int tid  = threadIdx.x;
    const int b    = blockIdx.x;
    const int lane = tid & 31;
    const int warp = tid >> 5;

    const float* __restrict__ xb = x + (size_t)b * (FEAT * FEAT);

    // ---- (1) SAT build (padded stride 116; cols 113-115 stay zero) --------
    for (int k = tid; k < SATN * SATP; k += NTH) {
        int i = k / SATP;
        int j = k - i * SATP;
        float v = 0.0f;
        if (i > 0 && j > 0 && j < SATN) v = xb[(i - 1) * FEAT + (j - 1)];
        S[k] = v;
    }
    __syncthreads();
    if (tid < SATN) {                     // row prefix
        float acc = 0.0f;
        float* row = S + tid * SATP;
        #pragma unroll 4
        for (int j = 1; j < SATN; j++) { acc += row[j]; row[j] = acc; }
    }
    __syncthreads();
    if (tid < SATN) {                     // column prefix (coalesced)
        float acc = 0.0f;
        #pragma unroll 4
        for (int i = 1; i < SATN; i++) {
            acc += S[i * SATP + tid];
            S[i * SATP + tid] = acc;
        }
    }
    __syncthreads();

    // ---- (2) scoring, warp-per-row: ws -> gmem, (rowmax,rowarg) -> smem ----
    float* ws = out + 2 * (NBATCH * PROPN) + (size_t)b * NTOTAL;

    #pragma unroll
    for (int r = 0; r < NRAT; r++) {
        const int rh = cRH(r), rw = cRW(r);
        const int nr = SATN - rh, nc = SATN - rw;
        const int nq = (nc + 3) >> 2;     // lane q covers windows 4q..4q+3
        const float inv = 1.0f / (float)(rh * rw);
        const int base = cBASE(r), R_ = rh * SATP, rowb = cXO(r);
        for (int xi = warp; xi < nr; xi += 32) {
            float ls = NEGINF; int li = 0x7fffffff;
            if (lane < nq) {
                int a = xi * SATP + (lane << 2);   // 16B-aligned
                float4 v0 = *(const float4*)(S + a);
                float4 v1 = *(const float4*)(S + a + rw);
                float4 v2 = *(const float4*)(S + a + R_);
                float4 v3 = *(const float4*)(S + a + R_ + rw);
                float s0 = (v3.x - v1.x - v2.x + v0.x) * inv;
                float s1 = (v3.y - v1.y - v2.y + v0.y) * inv;
                float s2 = (v3.z - v1.z - v2.z + v0.z) * inv;
                float s3 = (v3.w - v1.w - v2.w + v0.w) * inv;
                int off = base + xi * nc + (lane << 2);
                bool full = (lane != nq - 1);      // nc % 4 == 1
                ws[off] = s0;
                ls = s0; li = off;
                if (full) {
                    ws[off + 1] = s1;
                    ws[off + 2] = s2;
                    ws[off + 3] = s3;
                    if (s1 > ls) { ls = s1; li = off + 1; }
                    if (s2 > ls) { ls = s2; li = off + 2; }
                    if (s3 > ls) { ls = s3; li = off + 3; }
                }
            }
            wmerge(ls, li);
            if (lane == 0) { RMAX[rowb + xi] = ls; RARG[rowb + xi] = li; }
        }
    }
    __syncthreads();

    // ---- (3) pick0: reduce cached row maxima per group ----------------------
    float cs[3]; int ci[3];
    {
        #pragma unroll
        for (int g = 0; g < 3; g++) { cs[g] = NEGINF; ci[g] = 0x7fffffff; }
        if (tid < 291)       { cs[0] = RMAX[tid];       ci[0] = RARG[tid]; }
        if (tid < 558 - 291) { cs[1] = RMAX[291 + tid]; ci[1] = RARG[291 + tid]; }
        if (tid < 1121 - 558){ cs[2] = RMAX[558 + tid]; ci[2] = RARG[558 + tid]; }
        #pragma unroll
        for (int g = 0; g < 3; g++) wmerge(cs[g], ci[g]);
        if (lane == 0)
            #pragma unroll
            for (int g = 0; g < 3; g++) { red_s[g][warp] = cs[g]; red_i[g][warp] = ci[g]; }
        __syncthreads();
        if (warp == 0) {
            float bb[3]; int ii[3];
            #pragma unroll
            for (int g = 0; g < 3; g++) { bb[g] = red_s[g][lane]; ii[g] = red_i[g][lane]; wmerge(bb[g], ii[g]); }
            if (lane == 0) {
                const int slot[3] = {0, 2, 5};
                #pragma unroll
                for (int g = 0; g < 3; g++) {
                    out[b * PROPN + slot[g]] = (float)ii[g];
                    out[NBATCH * PROPN + b * PROPN + slot[g]] = bb[g];
                    decode_box(ii[g], boxsm[g], &sarea[g]);
                }
            }
        }
        __syncthreads();
    }

    // prior boxes (registers, from smem)
    float p0x0 = boxsm[0][0], p0y0 = boxsm[0][1], p0x1 = boxsm[0][2], p0y1 = boxsm[0][3];
    float p1x0 = boxsm[1][0], p1y0 = boxsm[1][1], p1x1 = boxsm[1][2], p1y1 = boxsm[1][3];
    float p2x0 = boxsm[2][0], p2y0 = boxsm[2][1], p2x1 = boxsm[2][2], p2y1 = boxsm[2][3];
    float sa0 = sarea[0], sa1 = sarea[1], sa2 = sarea[2];

    // ---- (4) pick1 for all 3 groups ----------------------------------------
    bool  df[3]; float rm[3];
    pick_phase1<0, 3, 1>(RMAX, RARG, p0x0, p0x1, 0, 0, tid, cs[0], ci[0], df[0], rm[0]);
    pick_phase1<3, 6, 1>(RMAX, RARG, p1x0, p1x1, 0, 0, tid, cs[1], ci[1], df[1], rm[1]);
    pick_phase1<6, 13, 1>(RMAX, RARG, p2x0, p2x1, 0, 0, tid, cs[2], ci[2], df[2], rm[2]);
    {   // reduce -> LB per group
        #pragma unroll
        for (int g = 0; g < 3; g++) wmerge(cs[g], ci[g]);
        if (lane == 0)
            #pragma unroll
            for (int g = 0; g < 3; g++) { red_s[g][warp] = cs[g]; red_i[g][warp] = ci[g]; }
        __syncthreads();
        if (warp == 0) {
            float bb[3]; int ii[3];
            #pragma unroll
            for (int g = 0; g < 3; g++) { bb[g] = red_s[g][lane]; ii[g] = red_i[g][lane]; wmerge(bb[g], ii[g]); }
            if (lane == 0)
                #pragma unroll
                for (int g = 0; g < 3; g++) { LBs[g] = bb[g]; LBi[g] = ii[g]; }
        }
        __syncthreads();
    }
    pick_phase2<0, 3, 1>(S, p0x0, p0x1, p0y0, p0y1, sa0, 0,0,0,0,0,
                         tid, df[0], rm[0], LBs[0], LBi[0], cs[0], ci[0]);
    pick_phase2<3, 6, 1>(S, p1x0, p1x1, p1y0, p1y1, sa1, 0,0,0,0,0,
                         tid, df[1], rm[1], LBs[1], LBi[1], cs[1], ci[1]);
    pick_phase2<6, 13, 1>(S, p2x0, p2x1, p2y0, p2y1, sa2, 0,0,0,0,0,
                          tid, df[2], rm[2], LBs[2], LBi[2], cs[2], ci[2]);
    {   // final reduce, write pick1 outputs, decode g1's winner
        #pragma unroll
        for (int g = 0; g < 3; g++) wmerge(cs[g], ci[g]);
        if (lane == 0)
            #pragma unroll
            for (int g = 0; g < 3; g++) { red_s[g][warp] = cs[g]; red_i[g][warp] = ci[g]; }
        __syncthreads();
        if (warp == 0) {
            float bb[3]; int ii[3];
            #pragma unroll
            for (int g = 0; g < 3; g++) { bb[g] = red_s[g][lane]; ii[g] = red_i[g][lane]; wmerge(bb[g], ii[g]); }
            if (lane == 0) {
                const int slot[3] = {1, 3, 6};
                #pragma unroll
                for (int g = 0; g < 3; g++) {
                    out[b * PROPN + slot[g]] = (float)ii[g];
                    out[NBATCH * PROPN + b * PROPN + slot[g]] = bb[g];
                }
                decode_box(ii[1], boxsm[3], &sarea[3]);
            }
        }
        __syncthreads();
    }

    // ---- (5) g1 pick2 (two priors) ------------------------------------------
    float p3x0 = boxsm[3][0], p3y0 = boxsm[3][1], p3x1 = boxsm[3][2], p3y1 = boxsm[3][3];
    float sa3 = sarea[3];
    float c2s; int c2i; bool d2; float r2;
    pick_phase1<3, 6, 2>(RMAX, RARG, p1x0, p1x1, p3x0, p3x1, tid, c2s, c2i, d2, r2);
    {
        wmerge(c2s, c2i);
        if (lane == 0) { red_s[0][warp] = c2s; red_i[0][warp] = c2i; }
        __syncthreads();
        if (warp == 0) {
            c2s = red_s[0][lane]; c2i = red_i[0][lane];
            wmerge(c2s, c2i);
            if (lane == 0) { LBs[0] = c2s; LBi[0] = c2i; }
        }
        __syncthreads();
    }
    pick_phase2<3, 6, 2>(S, p1x0, p1x1, p1y0, p1y1, sa1,
                         p3x0, p3x1, p3y0, p3y1, sa3,
                         tid, d2, r2, LBs[0], LBi[0], c2s, c2i);
    {
        wmerge(c2s, c2i);
        if (lane == 0) { red_s[0][warp] = c2s; red_i[0][warp] = c2i; }
        __syncthreads();
        if (warp == 0) {
            c2s = red_s[0][lane]; c2i = red_i[0][lane];
            wmerge(c2s, c2i);
            if (lane == 0) {
                out[b * PROPN + 4] = (float)c2i;
                out[NBATCH * PROPN + b * PROPN + 4] = c2s;
            }
        }
    }
}

extern "C" void kernel_launch(void* const* d_in, const int* in_sizes, int n_in,
                              void* d_out, int out_size) {
    const float* x = (const float*)d_in[0];
    float* out = (float*)d_out;
    (void)in_sizes; (void)n_in; (void)out_size;

    const int smem = SMEM_FLOATS * (int)sizeof(float);  // 61400 B
    cudaFuncSetAttribute(appm_kernel, cudaFuncAttributeMaxDynamicSharedMemorySize, smem);
    appm_kernel<<<NBATCH, NTH, smem>>>(x, out);
}